// round 11
// baseline (speedup 1.0000x reference)
#include <cuda_runtime.h>
#include <cstdint>

#define NB   64
#define NT   512
#define NIN  256
#define NH   512
#define NOUT 256

// ---- static device scratch (no runtime allocation) --------------------------
__device__ float  g_xp[NB * NT * NH];
__device__ float  g_out0[NB * NT * NH];
__device__ float  g_hfin[NB][NH];        // final hidden, scalar layout for proj

// ---- recurrence config ------------------------------------------------------
#define G_J 16                // CTAs per cluster (j-slices of 32)
#define NCTA 256              // 16 batch groups x 16 -> 2 CTAs/SM (indep clusters)
#define CTA_J 32
#define RTHREADS 256          // 8 warps; warp = 4-j group, lane = k subset

// ---- f32x2 packed helpers ---------------------------------------------------
typedef unsigned long long u64t;
__device__ __forceinline__ u64t bcast2(float w) {
    u64t d; unsigned u = __float_as_uint(w);
    asm("mov.b64 %0, {%1, %1};" : "=l"(d) : "r"(u));
    return d;
}
__device__ __forceinline__ u64t fmax2(u64t a, u64t b, u64t c) {
    u64t d; asm("fma.rn.f32x2 %0, %1, %2, %3;" : "=l"(d) : "l"(a), "l"(b), "l"(c));
    return d;
}
__device__ __forceinline__ u64t addx2(u64t a, u64t b) {
    u64t d; asm("add.rn.f32x2 %0, %1, %2;" : "=l"(d) : "l"(a), "l"(b));
    return d;
}
__device__ __forceinline__ float2 unpk2(u64t v) {
    unsigned lo, hi; asm("mov.b64 {%0, %1}, %2;" : "=r"(lo), "=r"(hi) : "l"(v));
    return make_float2(__uint_as_float(lo), __uint_as_float(hi));
}
__device__ __forceinline__ u64t pk2(float x, float y) {
    u64t d; asm("mov.b64 %0, {%1, %2};" : "=l"(d) : "r"(__float_as_uint(x)), "r"(__float_as_uint(y)));
    return d;
}

// ---- DSMEM helpers ----------------------------------------------------------
__device__ __forceinline__ uint32_t smem_u32(const void* p) {
    return (uint32_t)__cvta_generic_to_shared(p);
}
__device__ __forceinline__ void st_cluster_b64(uint32_t local_addr, int rank, u64t v) {
    uint32_t ra;
    asm volatile("mapa.shared::cluster.u32 %0, %1, %2;" : "=r"(ra) : "r"(local_addr), "r"(rank));
    asm volatile("st.shared::cluster.b64 [%0], %1;" :: "r"(ra), "l"(v) : "memory");
}
// FUSED arrive+wait — measured fastest (R5/R9). Do not split (R7/R8 regression).
__device__ __forceinline__ void cluster_sync_hw() {
    asm volatile("barrier.cluster.arrive.aligned;" ::: "memory");   // release
    asm volatile("barrier.cluster.wait.aligned;"   ::: "memory");   // acquire
}

// h_new[b][j] = tanh( xp[b][t][j] + sum_k h[b][k]*Whh[j][k] )
// Cluster (16 CTAs) = one batch group of 4 batches; CTA rank gj owns j-slice
// [gj*32,+32). Full h (batch-pair layout) in each CTA's SMEM; DSMEM scatter +
// fused cluster sync per step. 2 CTAs/SM from DIFFERENT clusters -> one
// cluster's barrier wait overlaps the other's compute.
__global__ void __launch_bounds__(RTHREADS, 2) __cluster_dims__(G_J, 1, 1)
rnn_kernel(const float* __restrict__ xp, const float* __restrict__ Whh,
           float* __restrict__ outseq, int store_out)
{
    __shared__ float2 s_h[2][2][NH];    // [buf][pair(b01/b23)][j]  (16 KB)

    const int tid    = threadIdx.x;
    const int w      = tid >> 5;                 // 0..7
    const int lane   = tid & 31;
    const int gb     = blockIdx.x >> 4;          // batch group / cluster id
    const int gj     = blockIdx.x & 15;          // rank within cluster
    const int b_base = gb * 4;
    const int j_base = gj * CTA_J;

    // ---- W slice in registers: wreg[kk][i] = Whh[j_base+w*4+i][lane+32kk] ---
    float wreg[16][4];
    #pragma unroll
    for (int i = 0; i < 4; i++) {
        const float* wrow = Whh + (j_base + w * 4 + i) * NH + lane;
        #pragma unroll
        for (int kk = 0; kk < 16; kk++)
            wreg[kk][i] = __ldg(wrow + 32 * kk);
    }

    // zero initial h buffer (buf 0), local only
    for (int idx = tid; idx < NH; idx += RTHREADS) {
        s_h[0][0][idx] = make_float2(0.f, 0.f);
        s_h[0][1][idx] = make_float2(0.f, 0.f);
    }
    __syncthreads();

    // thread's output after reduce: acc index m_fin from lane bits 4,3,2
    const int m_fin = 4 * ((lane >> 4) & 1) + 2 * ((lane >> 3) & 1) + ((lane >> 2) & 1);
    const int i_fin = m_fin >> 1;                 // j offset within warp group
    const int p_fin = m_fin & 1;                  // batch pair (b01 vs b23)
    const int jglb  = j_base + w * 4 + i_fin;     // global j (0..511)
    const int bb0   = b_base + p_fin * 2;
    const uint32_t dst_addr[2] = { smem_u32(&s_h[0][p_fin][jglb]),
                                   smem_u32(&s_h[1][p_fin][jglb]) };
    const int q  = lane & 3;                      // 4 holder lanes per value
    const int r0 = q * 4;                         // each covers 4 of 16 ranks

    // ensure all cluster CTAs are launched (peer SMEM valid) before DSMEM use
    cluster_sync_hw();

    #pragma unroll 1
    for (int t = 0; t < NT; ++t) {
        const int cur = t & 1, nxt = cur ^ 1;

        // xp prefetch for this thread's outputs (barrier-independent)
        const int rowA = (bb0 * NT + t) * NH + jglb;
        const int rowB = ((bb0 + 1) * NT + t) * NH + jglb;
        const float xvA = __ldg(xp + rowA);
        const float xvB = __ldg(xp + rowB);

        // ---- packed-FMA partials over this lane's k subset ------------------
        u64t a[8];
        #pragma unroll
        for (int m = 0; m < 8; m++) a[m] = 0ull;

        #pragma unroll
        for (int kk = 0; kk < 16; kk++) {
            const int k = lane + 32 * kk;
            const u64t h01 = *(const u64t*)&s_h[cur][0][k];
            const u64t h23 = *(const u64t*)&s_h[cur][1][k];
            #pragma unroll
            for (int i = 0; i < 4; i++) {
                const u64t wp = bcast2(wreg[kk][i]);
                a[i * 2 + 0] = fmax2(wp, h01, a[i * 2 + 0]);
                a[i * 2 + 1] = fmax2(wp, h23, a[i * 2 + 1]);
            }
        }

        // ---- in-warp reduce: 3 split rounds (8->1) + 2 allreduce rounds -----
        u64t v4[4];
        #pragma unroll
        for (int m = 0; m < 4; m++) {
            const u64t send = (lane & 16) ? a[m] : a[m + 4];
            const u64t kept = (lane & 16) ? a[m + 4] : a[m];
            v4[m] = addx2(kept, __shfl_xor_sync(0xffffffffu, send, 16));
        }
        u64t v2[2];
        #pragma unroll
        for (int m = 0; m < 2; m++) {
            const u64t send = (lane & 8) ? v4[m] : v4[m + 2];
            const u64t kept = (lane & 8) ? v4[m + 2] : v4[m];
            v2[m] = addx2(kept, __shfl_xor_sync(0xffffffffu, send, 8));
        }
        u64t v1;
        {
            const u64t send = (lane & 4) ? v2[0] : v2[1];
            const u64t kept = (lane & 4) ? v2[1] : v2[0];
            v1 = addx2(kept, __shfl_xor_sync(0xffffffffu, send, 4));
        }
        v1 = addx2(v1, __shfl_xor_sync(0xffffffffu, v1, 2));  // k-merge (bit1)
        v1 = addx2(v1, __shfl_xor_sync(0xffffffffu, v1, 1));  // k-merge (bit0)

        // ---- activation -----------------------------------------------------
        const float2 s  = unpk2(v1);
        const float  h0 = tanhf(s.x + xvA);
        const float  h1 = tanhf(s.y + xvB);
        const u64t   hv = pk2(h0, h1);

        // side outputs (one of the 4 holder lanes)
        if (q == 1) {
            if (store_out) { outseq[rowA] = h0; outseq[rowB] = h1; }
            if (t == NT - 1) { g_hfin[bb0][jglb] = h0; g_hfin[bb0 + 1][jglb] = h1; }
        }

        if (t < NT - 1) {
            // scatter (h0,h1) into all 16 cluster CTAs' buf[nxt]; the 4 holder
            // lanes of each value split the 16 destination ranks (4 each)
            const uint32_t da = dst_addr[nxt];
            #pragma unroll
            for (int r = 0; r < 4; r++)
                st_cluster_b64(da, r0 + r, hv);
            cluster_sync_hw();   // fused release + acquire (measured fastest)
        }
    }
}

// ---- tf32 tensor-core GEMM: C[M,N] = A[M,K] @ B[N,K]^T + bias1 (+bias2) -----
// mma.sync.m16n8k8 tf32. CTA tile 128x64, BK=32, 256 thr = 8 warps (2m x 4n).
// Next-tile register prefetch hides GMEM latency under the MMA loop.
#define TBM 128
#define TBN 64
#define TBK 32
#define TPAD 4

__device__ __forceinline__ unsigned tf32b(float f) {
    unsigned r; asm("cvt.rna.tf32.f32 %0, %1;" : "=r"(r) : "f"(f));
    return r;
}

__global__ void __launch_bounds__(256)
gemm_tf32_nt_bias(const float* __restrict__ A, const float* __restrict__ B,
                  const float* __restrict__ bias1, const float* __restrict__ bias2,
                  float* __restrict__ C, int M, int N, int K)
{
    __shared__ unsigned As[TBK][TBM + TPAD];   // tf32 bits, [k][m]
    __shared__ unsigned Bs[TBK][TBN + TPAD];   // tf32 bits, [k][n]

    const int tid    = threadIdx.x;
    const int warp   = tid >> 5;
    const int lane   = tid & 31;
    const int warp_m = warp >> 2;          // 0..1 -> m offset *64
    const int warp_n = warp & 3;           // 0..3 -> n offset *16
    const int gid    = lane >> 2;          // 0..7
    const int tig    = lane & 3;           // 0..3

    const int m0 = blockIdx.x * TBM;
    const int n0 = blockIdx.y * TBN;

    const int lrA = tid >> 1;              // m row 0..127
    const int lcA = (tid & 1) * 16;        // k col base
    const int lrB = tid >> 2;              // n row 0..63
    const int lcB = (tid & 3) * 8;         // k col base

    float acc[4][2][4];
    #pragma unroll
    for (int mi = 0; mi < 4; mi++)
        #pragma unroll
        for (int ni = 0; ni < 2; ni++)
            #pragma unroll
            for (int c = 0; c < 4; c++) acc[mi][ni][c] = 0.f;

    // preload tile 0 into registers
    float4 a4[4], b4[2];
    #pragma unroll
    for (int c = 0; c < 4; c++)
        a4[c] = *(const float4*)(A + (m0 + lrA) * K + lcA + c * 4);
    #pragma unroll
    for (int c = 0; c < 2; c++)
        b4[c] = *(const float4*)(B + (n0 + lrB) * K + lcB + c * 4);

    for (int k0 = 0; k0 < K; k0 += TBK) {
        __syncthreads();
        #pragma unroll
        for (int c = 0; c < 4; c++) {
            As[lcA + c * 4 + 0][lrA] = tf32b(a4[c].x);
            As[lcA + c * 4 + 1][lrA] = tf32b(a4[c].y);
            As[lcA + c * 4 + 2][lrA] = tf32b(a4[c].z);
            As[lcA + c * 4 + 3][lrA] = tf32b(a4[c].w);
        }
        #pragma unroll
        for (int c = 0; c < 2; c++) {
            Bs[lcB + c * 4 + 0][lrB] = tf32b(b4[c].x);
            Bs[lcB + c * 4 + 1][lrB] = tf32b(b4[c].y);
            Bs[lcB + c * 4 + 2][lrB] = tf32b(b4[c].z);
            Bs[lcB + c * 4 + 3][lrB] = tf32b(b4[c].w);
        }
        __syncthreads();

        // prefetch NEXT tile while computing this one
        if (k0 + TBK < K) {
            #pragma unroll
            for (int c = 0; c < 4; c++)
                a4[c] = *(const float4*)(A + (m0 + lrA) * K + k0 + TBK + lcA + c * 4);
            #pragma unroll
            for (int c = 0; c < 2; c++)
                b4[c] = *(const float4*)(B + (n0 + lrB) * K + k0 + TBK + lcB + c * 4);
        }

        #pragma unroll
        for (int ks = 0; ks < TBK / 8; ks++) {
            const int kb = ks * 8;
            unsigned af[4][4], bf[2][2];
            #pragma unroll
            for (int mi = 0; mi < 4; mi++) {
                const int mr = warp_m * 64 + mi * 16;
                af[mi][0] = As[kb + tig    ][mr + gid];
                af[mi][1] = As[kb + tig    ][mr + gid + 8];
                af[mi][2] = As[kb + tig + 4][mr + gid];
                af[mi][3] = As[kb + tig + 4][mr + gid + 8];
            }
            #pragma unroll
            for (int ni = 0; ni < 2; ni++) {
                const int nc = warp_n * 16 + ni * 8;
                bf[ni][0] = Bs[kb + tig    ][nc + gid];
                bf[ni][1] = Bs[kb + tig + 4][nc + gid];
            }
            #pragma unroll
            for (int mi = 0; mi < 4; mi++)
                #pragma unroll
                for (int ni = 0; ni < 2; ni++) {
                    asm volatile(
                        "mma.sync.aligned.m16n8k8.row.col.f32.tf32.tf32.f32 "
                        "{%0,%1,%2,%3}, {%4,%5,%6,%7}, {%8,%9}, {%0,%1,%2,%3};"
                        : "+f"(acc[mi][ni][0]), "+f"(acc[mi][ni][1]),
                          "+f"(acc[mi][ni][2]), "+f"(acc[mi][ni][3])
                        : "r"(af[mi][0]), "r"(af[mi][1]), "r"(af[mi][2]), "r"(af[mi][3]),
                          "r"(bf[ni][0]), "r"(bf[ni][1]));
                }
        }
    }

    #pragma unroll
    for (int ni = 0; ni < 2; ni++) {
        const int col = n0 + warp_n * 16 + ni * 8 + tig * 2;
        float bv0 = bias1 ? bias1[col]     : 0.f;
        float bv1 = bias1 ? bias1[col + 1] : 0.f;
        if (bias2) { bv0 += bias2[col]; bv1 += bias2[col + 1]; }
        #pragma unroll
        for (int mi = 0; mi < 4; mi++) {
            const int row = m0 + warp_m * 64 + mi * 16 + gid;
            *(float2*)(C + row * N + col) =
                make_float2(acc[mi][ni][0] + bv0, acc[mi][ni][1] + bv1);
            *(float2*)(C + (row + 8) * N + col) =
                make_float2(acc[mi][ni][2] + bv0, acc[mi][ni][3] + bv1);
        }
    }
}

// ---- small fp32 GEMM (64x64 tile) for the final projection (M=64) -----------
#define BM 64
#define BN 64
#define BK 16

__global__ void __launch_bounds__(256)
gemm_nt_bias(const float* __restrict__ A, const float* __restrict__ B,
             const float* __restrict__ bias1, const float* __restrict__ bias2,
             float* __restrict__ C, int M, int N, int K)
{
    __shared__ __align__(16) float As[BK][BM];
    __shared__ __align__(16) float Bs[BK][BN];

    const int tid = threadIdx.x;
    const int m0 = blockIdx.x * BM;
    const int n0 = blockIdx.y * BN;
    const int tx = tid & 15;
    const int ty = tid >> 4;
    const int lr = tid >> 2;
    const int lc = tid & 3;

    float acc[4][4];
    #pragma unroll
    for (int i = 0; i < 4; i++)
        #pragma unroll
        for (int j = 0; j < 4; j++) acc[i][j] = 0.f;

    for (int kk0 = 0; kk0 < K; kk0 += BK) {
        const float4 av = *(const float4*)(A + (m0 + lr) * K + kk0 + lc * 4);
        const float4 bv = *(const float4*)(B + (n0 + lr) * K + kk0 + lc * 4);
        __syncthreads();
        As[lc*4+0][lr] = av.x; As[lc*4+1][lr] = av.y;
        As[lc*4+2][lr] = av.z; As[lc*4+3][lr] = av.w;
        Bs[lc*4+0][lr] = bv.x; Bs[lc*4+1][lr] = bv.y;
        Bs[lc*4+2][lr] = bv.z; Bs[lc*4+3][lr] = bv.w;
        __syncthreads();

        #pragma unroll
        for (int k = 0; k < BK; ++k) {
            const float4 a = *(const float4*)(&As[k][ty * 4]);
            const float4 b = *(const float4*)(&Bs[k][tx * 4]);
            const float avv[4] = {a.x, a.y, a.z, a.w};
            const float bvv[4] = {b.x, b.y, b.z, b.w};
            #pragma unroll
            for (int i = 0; i < 4; i++)
                #pragma unroll
                for (int j = 0; j < 4; j++)
                    acc[i][j] += avv[i] * bvv[j];
        }
    }

    #pragma unroll
    for (int i = 0; i < 4; i++) {
        const int m = m0 + ty * 4 + i;
        const int n = n0 + tx * 4;
        float bsv[4];
        #pragma unroll
        for (int j = 0; j < 4; j++) {
            bsv[j] = bias1 ? bias1[n + j] : 0.f;
            if (bias2) bsv[j] += bias2[n + j];
        }
        float4 o;
        o.x = acc[i][0] + bsv[0];
        o.y = acc[i][1] + bsv[1];
        o.z = acc[i][2] + bsv[2];
        o.w = acc[i][3] + bsv[3];
        *(float4*)(C + m * N + n) = o;
    }
}

// ---- launch -----------------------------------------------------------------
extern "C" void kernel_launch(void* const* d_in, const int* in_sizes, int n_in,
                              void* d_out, int out_size)
{
    const float* x     = (const float*)d_in[0];
    const float* W_ih0 = (const float*)d_in[1];
    const float* W_hh0 = (const float*)d_in[2];
    const float* b_ih0 = (const float*)d_in[3];
    const float* b_hh0 = (const float*)d_in[4];
    const float* W_ih1 = (const float*)d_in[5];
    const float* W_hh1 = (const float*)d_in[6];
    const float* b_ih1 = (const float*)d_in[7];
    const float* b_hh1 = (const float*)d_in[8];
    const float* W_out = (const float*)d_in[9];
    const float* b_out = (const float*)d_in[10];
    float* out = (float*)d_out;

    float *xp, *out0, *hfin;
    cudaGetSymbolAddress((void**)&xp,   g_xp);
    cudaGetSymbolAddress((void**)&out0, g_out0);
    cudaGetSymbolAddress((void**)&hfin, g_hfin);

    // 16-wide clusters require the non-portable opt-in (checked at launch)
    cudaFuncSetAttribute(rnn_kernel,
                         cudaFuncAttributeNonPortableClusterSizeAllowed, 1);

    const int M = NB * NT;  // 32768

    // xp0 = x @ W_ih0^T + b_ih0 + b_hh0   (tf32 tensor cores, prefetched)
    {
        dim3 grid(M / TBM, NH / TBN);
        gemm_tf32_nt_bias<<<grid, 256>>>(x, W_ih0, b_ih0, b_hh0, xp, M, NH, NIN);
    }
    // layer 0 recurrence (stores full sequence)
    rnn_kernel<<<NCTA, RTHREADS>>>(xp, W_hh0, out0, 1);

    // xp1 = out0 @ W_ih1^T + b_ih1 + b_hh1   (tf32 tensor cores, prefetched)
    {
        dim3 grid(M / TBM, NH / TBN);
        gemm_tf32_nt_bias<<<grid, 256>>>(out0, W_ih1, b_ih1, b_hh1, xp, M, NH, NH);
    }
    // layer 1 recurrence (final hidden -> g_hfin)
    rnn_kernel<<<NCTA, RTHREADS>>>(xp, W_hh1, nullptr, 0);

    // out = h_last @ W_out^T + b_out  (tiny, fp32)
    {
        dim3 grid(NB / BM, NOUT / BN);
        gemm_nt_bias<<<grid, 256>>>(hfin, W_out, b_out, nullptr, out, NB, NOUT, NH);
    }
}

// round 13
// speedup vs baseline: 1.1536x; 1.1536x over previous
#include <cuda_runtime.h>
#include <cstdint>

#define NB   64
#define NT   512
#define NIN  256
#define NH   512
#define NOUT 256

// ---- static device scratch (no runtime allocation) --------------------------
__device__ float  g_xp[NB * NT * NH];
__device__ float  g_out0[NB * NT * NH];
__device__ float  g_hfin[NB][NH];        // final hidden, scalar layout for proj

// ---- recurrence config ------------------------------------------------------
#define G_J 8                 // CTAs per cluster (j-slices)
#define NCTA 128              // 16 clusters x 8
#define CTA_J 64
#define RTHREADS 256          // 8 warps; warp = 8-j group, lane = k-pair subset

// ---- f32x2 packed helpers ---------------------------------------------------
typedef unsigned long long u64t;
__device__ __forceinline__ u64t fmax2(u64t a, u64t b, u64t c) {
    u64t d; asm("fma.rn.f32x2 %0, %1, %2, %3;" : "=l"(d) : "l"(a), "l"(b), "l"(c));
    return d;
}
__device__ __forceinline__ u64t addx2(u64t a, u64t b) {
    u64t d; asm("add.rn.f32x2 %0, %1, %2;" : "=l"(d) : "l"(a), "l"(b));
    return d;
}
__device__ __forceinline__ float2 unpk2(u64t v) {
    unsigned lo, hi; asm("mov.b64 {%0, %1}, %2;" : "=r"(lo), "=r"(hi) : "l"(v));
    return make_float2(__uint_as_float(lo), __uint_as_float(hi));
}

// ---- DSMEM helpers ----------------------------------------------------------
__device__ __forceinline__ uint32_t smem_u32(const void* p) {
    return (uint32_t)__cvta_generic_to_shared(p);
}
__device__ __forceinline__ void st_cluster_b32(uint32_t local_addr, int rank, float v) {
    uint32_t ra;
    asm volatile("mapa.shared::cluster.u32 %0, %1, %2;" : "=r"(ra) : "r"(local_addr), "r"(rank));
    asm volatile("st.shared::cluster.b32 [%0], %1;" :: "r"(ra), "r"(__float_as_uint(v)) : "memory");
}
// FUSED arrive+wait — measured fastest (R5/R9). Do not split (R7/R8 regression).
__device__ __forceinline__ void cluster_sync_hw() {
    asm volatile("barrier.cluster.arrive.aligned;" ::: "memory");   // release
    asm volatile("barrier.cluster.wait.aligned;"   ::: "memory");   // acquire
}

// h_new[b][j] = tanh( xp[b][t][j] + sum_k h[b][k]*Whh[j][k] )
// R9 skeleton, k-packed math: accumulators hold (sum over even k, sum over odd
// k) f32x2 pairs; W pairs (W[j][k],W[j][k+1]) are register-resident u64 (no
// runtime movs) and h pairs load directly as LDS.64 from scalar per-batch rows.
__global__ void __launch_bounds__(RTHREADS, 1) __cluster_dims__(G_J, 1, 1)
rnn_kernel(const float* __restrict__ xp, const float* __restrict__ Whh,
           float* __restrict__ outseq, int store_out)
{
    __shared__ __align__(16) float s_h[2][4][NH];   // [buf][batch][j]  16 KB

    const int tid    = threadIdx.x;
    const int w      = tid >> 5;
    const int lane   = tid & 31;
    const int gb     = blockIdx.x >> 3;          // batch group / cluster id
    const int gj     = blockIdx.x & 7;           // rank within cluster
    const int b_base = gb * 4;
    const int j_base = gj * CTA_J;
    const int kbase  = 2 * lane;                 // this lane's k-pair base

    // ---- W k-pairs in registers: wpk[kk][i] = (W[j][k0],W[j][k0+1]),
    // j = j_base + w*8 + i, k0 = 2*lane + 64*kk. 8-byte aligned GMEM loads.
    u64t wpk[8][8];
    #pragma unroll
    for (int i = 0; i < 8; i++) {
        const float* wrow = Whh + (j_base + w * 8 + i) * NH + kbase;
        #pragma unroll
        for (int kk = 0; kk < 8; kk++)
            wpk[kk][i] = *(const u64t*)(wrow + 64 * kk);
    }

    // zero initial h buffer (buf 0), local only
    for (int idx = tid; idx < 4 * NH; idx += RTHREADS)
        ((float*)s_h[0])[idx] = 0.f;
    __syncthreads();

    // output mapping after reduce: lane bits 4,3,2 -> i ; bit1 -> batch pair
    const int i_fin = 4 * ((lane >> 4) & 1) + 2 * ((lane >> 3) & 1) + ((lane >> 2) & 1);
    const int pb    = (lane >> 1) & 1;            // batch-pair select
    const int jglb  = j_base + w * 8 + i_fin;     // global j (0..511)
    const int bA    = b_base + 2 * pb;            // first batch of the pair
    const uint32_t dstA[2] = { smem_u32(&s_h[0][2 * pb    ][jglb]),
                               smem_u32(&s_h[1][2 * pb    ][jglb]) };
    const uint32_t dstB[2] = { smem_u32(&s_h[0][2 * pb + 1][jglb]),
                               smem_u32(&s_h[1][2 * pb + 1][jglb]) };
    const int r0 = (lane & 1) ? 4 : 0;            // dup-lane parity splits ranks

    // peers' SMEM valid before any DSMEM store
    cluster_sync_hw();

    #pragma unroll 1
    for (int t = 0; t < NT; ++t) {
        const int cur = t & 1, nxt = cur ^ 1;

        // xp prefetch for this thread's outputs (barrier-independent)
        const int rowA = (bA * NT + t) * NH + jglb;
        const int rowB = ((bA + 1) * NT + t) * NH + jglb;
        const float xvA = __ldg(xp + rowA);
        const float xvB = __ldg(xp + rowB);

        // ---- k-packed FMA partials: a[i*4+b] = (sum_even_k, sum_odd_k) ------
        u64t a[32];
        #pragma unroll
        for (int m = 0; m < 32; m++) a[m] = 0ull;

        #pragma unroll
        for (int kk = 0; kk < 8; kk++) {
            const int k0v = kbase + 64 * kk;
            const u64t h0v = *(const u64t*)&s_h[cur][0][k0v];
            const u64t h1v = *(const u64t*)&s_h[cur][1][k0v];
            const u64t h2v = *(const u64t*)&s_h[cur][2][k0v];
            const u64t h3v = *(const u64t*)&s_h[cur][3][k0v];
            #pragma unroll
            for (int i = 0; i < 8; i++) {
                const u64t wv = wpk[kk][i];
                a[i * 4 + 0] = fmax2(wv, h0v, a[i * 4 + 0]);
                a[i * 4 + 1] = fmax2(wv, h1v, a[i * 4 + 1]);
                a[i * 4 + 2] = fmax2(wv, h2v, a[i * 4 + 2]);
                a[i * 4 + 3] = fmax2(wv, h3v, a[i * 4 + 3]);
            }
        }

        // ---- in-warp reduce-scatter: 4 split rounds (32->2) + 1 allreduce ---
        u64t v16[16];
        #pragma unroll
        for (int m = 0; m < 16; m++) {
            const u64t send = (lane & 16) ? a[m] : a[m + 16];
            const u64t kept = (lane & 16) ? a[m + 16] : a[m];
            v16[m] = addx2(kept, __shfl_xor_sync(0xffffffffu, send, 16));
        }
        u64t v8[8];
        #pragma unroll
        for (int m = 0; m < 8; m++) {
            const u64t send = (lane & 8) ? v16[m] : v16[m + 8];
            const u64t kept = (lane & 8) ? v16[m + 8] : v16[m];
            v8[m] = addx2(kept, __shfl_xor_sync(0xffffffffu, send, 8));
        }
        u64t v4[4];
        #pragma unroll
        for (int m = 0; m < 4; m++) {
            const u64t send = (lane & 4) ? v8[m] : v8[m + 4];
            const u64t kept = (lane & 4) ? v8[m + 4] : v8[m];
            v4[m] = addx2(kept, __shfl_xor_sync(0xffffffffu, send, 4));
        }
        u64t v2[2];
        #pragma unroll
        for (int m = 0; m < 2; m++) {
            const u64t send = (lane & 2) ? v4[m] : v4[m + 2];
            const u64t kept = (lane & 2) ? v4[m + 2] : v4[m];
            v2[m] = addx2(kept, __shfl_xor_sync(0xffffffffu, send, 2));
        }
        // allreduce across the dup-lane pair (k subsets), both outputs
        const u64t vA = addx2(v2[0], __shfl_xor_sync(0xffffffffu, v2[0], 1));
        const u64t vB = addx2(v2[1], __shfl_xor_sync(0xffffffffu, v2[1], 1));

        // ---- horizontal (even+odd) + activation -----------------------------
        const float2 sA = unpk2(vA);
        const float2 sB = unpk2(vB);
        const float  h0 = tanhf(sA.x + sA.y + xvA);   // (jglb, bA)
        const float  h1 = tanhf(sB.x + sB.y + xvB);   // (jglb, bA+1)

        // side outputs (one of the 2 duplicate lanes)
        if (lane & 1) {
            if (store_out) { outseq[rowA] = h0; outseq[rowB] = h1; }
            if (t == NT - 1) { g_hfin[bA][jglb] = h0; g_hfin[bA + 1][jglb] = h1; }
        }

        if (t < NT - 1) {
            // scatter both scalars into all 8 cluster CTAs' buf[nxt]
            const uint32_t daA = dstA[nxt], daB = dstB[nxt];
            #pragma unroll
            for (int r = 0; r < 4; r++) {
                st_cluster_b32(daA, r0 + r, h0);
                st_cluster_b32(daB, r0 + r, h1);
            }
            cluster_sync_hw();   // fused release + acquire (measured fastest)
        }
    }
}

// ---- tf32 tensor-core GEMM: C[M,N] = A[M,K] @ B[N,K]^T + bias1 (+bias2) -----
// mma.sync.m16n8k8 tf32. CTA tile 128x64, BK=32, 256 thr = 8 warps (2m x 4n).
#define TBM 128
#define TBN 64
#define TBK 32
#define TPAD 4

__device__ __forceinline__ unsigned tf32b(float f) {
    unsigned r; asm("cvt.rna.tf32.f32 %0, %1;" : "=r"(r) : "f"(f));
    return r;
}

__global__ void __launch_bounds__(256)
gemm_tf32_nt_bias(const float* __restrict__ A, const float* __restrict__ B,
                  const float* __restrict__ bias1, const float* __restrict__ bias2,
                  float* __restrict__ C, int M, int N, int K)
{
    __shared__ unsigned As[TBK][TBM + TPAD];   // tf32 bits, [k][m]
    __shared__ unsigned Bs[TBK][TBN + TPAD];   // tf32 bits, [k][n]

    const int tid    = threadIdx.x;
    const int warp   = tid >> 5;
    const int lane   = tid & 31;
    const int warp_m = warp >> 2;          // 0..1 -> m offset *64
    const int warp_n = warp & 3;           // 0..3 -> n offset *16
    const int gid    = lane >> 2;          // 0..7
    const int tig    = lane & 3;           // 0..3

    const int m0 = blockIdx.x * TBM;
    const int n0 = blockIdx.y * TBN;

    const int lrA = tid >> 1;              // m row 0..127
    const int lcA = (tid & 1) * 16;        // k col base
    const int lrB = tid >> 2;              // n row 0..63
    const int lcB = (tid & 3) * 8;         // k col base

    float acc[4][2][4];
    #pragma unroll
    for (int mi = 0; mi < 4; mi++)
        #pragma unroll
        for (int ni = 0; ni < 2; ni++)
            #pragma unroll
            for (int c = 0; c < 4; c++) acc[mi][ni][c] = 0.f;

    for (int k0 = 0; k0 < K; k0 += TBK) {
        float4 a4[4], b4[2];
        #pragma unroll
        for (int c = 0; c < 4; c++)
            a4[c] = *(const float4*)(A + (m0 + lrA) * K + k0 + lcA + c * 4);
        #pragma unroll
        for (int c = 0; c < 2; c++)
            b4[c] = *(const float4*)(B + (n0 + lrB) * K + k0 + lcB + c * 4);

        __syncthreads();
        #pragma unroll
        for (int c = 0; c < 4; c++) {
            As[lcA + c * 4 + 0][lrA] = tf32b(a4[c].x);
            As[lcA + c * 4 + 1][lrA] = tf32b(a4[c].y);
            As[lcA + c * 4 + 2][lrA] = tf32b(a4[c].z);
            As[lcA + c * 4 + 3][lrA] = tf32b(a4[c].w);
        }
        #pragma unroll
        for (int c = 0; c < 2; c++) {
            Bs[lcB + c * 4 + 0][lrB] = tf32b(b4[c].x);
            Bs[lcB + c * 4 + 1][lrB] = tf32b(b4[c].y);
            Bs[lcB + c * 4 + 2][lrB] = tf32b(b4[c].z);
            Bs[lcB + c * 4 + 3][lrB] = tf32b(b4[c].w);
        }
        __syncthreads();

        #pragma unroll
        for (int ks = 0; ks < TBK / 8; ks++) {
            const int kb = ks * 8;
            unsigned af[4][4], bf[2][2];
            #pragma unroll
            for (int mi = 0; mi < 4; mi++) {
                const int mr = warp_m * 64 + mi * 16;
                af[mi][0] = As[kb + tig    ][mr + gid];
                af[mi][1] = As[kb + tig    ][mr + gid + 8];
                af[mi][2] = As[kb + tig + 4][mr + gid];
                af[mi][3] = As[kb + tig + 4][mr + gid + 8];
            }
            #pragma unroll
            for (int ni = 0; ni < 2; ni++) {
                const int nc = warp_n * 16 + ni * 8;
                bf[ni][0] = Bs[kb + tig    ][nc + gid];
                bf[ni][1] = Bs[kb + tig + 4][nc + gid];
            }
            #pragma unroll
            for (int mi = 0; mi < 4; mi++)
                #pragma unroll
                for (int ni = 0; ni < 2; ni++) {
                    asm volatile(
                        "mma.sync.aligned.m16n8k8.row.col.f32.tf32.tf32.f32 "
                        "{%0,%1,%2,%3}, {%4,%5,%6,%7}, {%8,%9}, {%0,%1,%2,%3};"
                        : "+f"(acc[mi][ni][0]), "+f"(acc[mi][ni][1]),
                          "+f"(acc[mi][ni][2]), "+f"(acc[mi][ni][3])
                        : "r"(af[mi][0]), "r"(af[mi][1]), "r"(af[mi][2]), "r"(af[mi][3]),
                          "r"(bf[ni][0]), "r"(bf[ni][1]));
                }
        }
    }

    #pragma unroll
    for (int ni = 0; ni < 2; ni++) {
        const int col = n0 + warp_n * 16 + ni * 8 + tig * 2;
        float bv0 = bias1 ? bias1[col]     : 0.f;
        float bv1 = bias1 ? bias1[col + 1] : 0.f;
        if (bias2) { bv0 += bias2[col]; bv1 += bias2[col + 1]; }
        #pragma unroll
        for (int mi = 0; mi < 4; mi++) {
            const int row = m0 + warp_m * 64 + mi * 16 + gid;
            *(float2*)(C + row * N + col) =
                make_float2(acc[mi][ni][0] + bv0, acc[mi][ni][1] + bv1);
            *(float2*)(C + (row + 8) * N + col) =
                make_float2(acc[mi][ni][2] + bv0, acc[mi][ni][3] + bv1);
        }
    }
}

// ---- small fp32 GEMM (64x64 tile) for the final projection (M=64) -----------
#define BM 64
#define BN 64
#define BK 16

__global__ void __launch_bounds__(256)
gemm_nt_bias(const float* __restrict__ A, const float* __restrict__ B,
             const float* __restrict__ bias1, const float* __restrict__ bias2,
             float* __restrict__ C, int M, int N, int K)
{
    __shared__ __align__(16) float As[BK][BM];
    __shared__ __align__(16) float Bs[BK][BN];

    const int tid = threadIdx.x;
    const int m0 = blockIdx.x * BM;
    const int n0 = blockIdx.y * BN;
    const int tx = tid & 15;
    const int ty = tid >> 4;
    const int lr = tid >> 2;
    const int lc = tid & 3;

    float acc[4][4];
    #pragma unroll
    for (int i = 0; i < 4; i++)
        #pragma unroll
        for (int j = 0; j < 4; j++) acc[i][j] = 0.f;

    for (int kk0 = 0; kk0 < K; kk0 += BK) {
        const float4 av = *(const float4*)(A + (m0 + lr) * K + kk0 + lc * 4);
        const float4 bv = *(const float4*)(B + (n0 + lr) * K + kk0 + lc * 4);
        __syncthreads();
        As[lc*4+0][lr] = av.x; As[lc*4+1][lr] = av.y;
        As[lc*4+2][lr] = av.z; As[lc*4+3][lr] = av.w;
        Bs[lc*4+0][lr] = bv.x; Bs[lc*4+1][lr] = bv.y;
        Bs[lc*4+2][lr] = bv.z; Bs[lc*4+3][lr] = bv.w;
        __syncthreads();

        #pragma unroll
        for (int k = 0; k < BK; ++k) {
            const float4 a = *(const float4*)(&As[k][ty * 4]);
            const float4 b = *(const float4*)(&Bs[k][tx * 4]);
            const float avv[4] = {a.x, a.y, a.z, a.w};
            const float bvv[4] = {b.x, b.y, b.z, b.w};
            #pragma unroll
            for (int i = 0; i < 4; i++)
                #pragma unroll
                for (int j = 0; j < 4; j++)
                    acc[i][j] += avv[i] * bvv[j];
        }
    }

    #pragma unroll
    for (int i = 0; i < 4; i++) {
        const int m = m0 + ty * 4 + i;
        const int n = n0 + tx * 4;
        float bsv[4];
        #pragma unroll
        for (int j = 0; j < 4; j++) {
            bsv[j] = bias1 ? bias1[n + j] : 0.f;
            if (bias2) bsv[j] += bias2[n + j];
        }
        float4 o;
        o.x = acc[i][0] + bsv[0];
        o.y = acc[i][1] + bsv[1];
        o.z = acc[i][2] + bsv[2];
        o.w = acc[i][3] + bsv[3];
        *(float4*)(C + m * N + n) = o;
    }
}

// ---- launch -----------------------------------------------------------------
extern "C" void kernel_launch(void* const* d_in, const int* in_sizes, int n_in,
                              void* d_out, int out_size)
{
    const float* x     = (const float*)d_in[0];
    const float* W_ih0 = (const float*)d_in[1];
    const float* W_hh0 = (const float*)d_in[2];
    const float* b_ih0 = (const float*)d_in[3];
    const float* b_hh0 = (const float*)d_in[4];
    const float* W_ih1 = (const float*)d_in[5];
    const float* W_hh1 = (const float*)d_in[6];
    const float* b_ih1 = (const float*)d_in[7];
    const float* b_hh1 = (const float*)d_in[8];
    const float* W_out = (const float*)d_in[9];
    const float* b_out = (const float*)d_in[10];
    float* out = (float*)d_out;

    float *xp, *out0, *hfin;
    cudaGetSymbolAddress((void**)&xp,   g_xp);
    cudaGetSymbolAddress((void**)&out0, g_out0);
    cudaGetSymbolAddress((void**)&hfin, g_hfin);

    const int M = NB * NT;  // 32768

    // xp0 = x @ W_ih0^T + b_ih0 + b_hh0   (tf32 tensor cores)
    {
        dim3 grid(M / TBM, NH / TBN);
        gemm_tf32_nt_bias<<<grid, 256>>>(x, W_ih0, b_ih0, b_hh0, xp, M, NH, NIN);
    }
    // layer 0 recurrence (stores full sequence)
    rnn_kernel<<<NCTA, RTHREADS>>>(xp, W_hh0, out0, 1);

    // xp1 = out0 @ W_ih1^T + b_ih1 + b_hh1   (tf32 tensor cores)
    {
        dim3 grid(M / TBM, NH / TBN);
        gemm_tf32_nt_bias<<<grid, 256>>>(out0, W_ih1, b_ih1, b_hh1, xp, M, NH, NH);
    }
    // layer 1 recurrence (final hidden -> g_hfin)
    rnn_kernel<<<NCTA, RTHREADS>>>(xp, W_hh1, nullptr, 0);

    // out = h_last @ W_out^T + b_out  (tiny, fp32)
    {
        dim3 grid(NB / BM, NOUT / BN);
        gemm_nt_bias<<<grid, 256>>>(hfin, W_out, b_out, nullptr, out, NB, NOUT, NH);
    }
}

// round 14
// speedup vs baseline: 1.4926x; 1.2938x over previous
#include <cuda_runtime.h>
#include <cstdint>

#define NB   64
#define NT   512
#define NIN  256
#define NH   512
#define NOUT 256

// ---- static device scratch (no runtime allocation) --------------------------
__device__ float  g_xp[NB * NT * NH];
__device__ float  g_out0[NB * NT * NH];
__device__ float  g_hfin[NB][NH];        // final hidden, scalar layout for proj

// ---- recurrence config ------------------------------------------------------
#define G_J 8                 // CTAs per cluster (j-slices)
#define NCTA 128              // 16 clusters x 8
#define CTA_J 64
#define RTHREADS 256          // 8 warps; warp = 8-j group, lane = k subset
#define STEP_TX  8192         // bytes of h received per CTA per step

// ---- f32x2 packed helpers ---------------------------------------------------
typedef unsigned long long u64t;
__device__ __forceinline__ u64t bcast2(float w) {
    u64t d; unsigned u = __float_as_uint(w);
    asm("mov.b64 %0, {%1, %1};" : "=l"(d) : "r"(u));
    return d;
}
__device__ __forceinline__ u64t fmax2(u64t a, u64t b, u64t c) {
    u64t d; asm("fma.rn.f32x2 %0, %1, %2, %3;" : "=l"(d) : "l"(a), "l"(b), "l"(c));
    return d;
}
__device__ __forceinline__ u64t addx2(u64t a, u64t b) {
    u64t d; asm("add.rn.f32x2 %0, %1, %2;" : "=l"(d) : "l"(a), "l"(b));
    return d;
}
__device__ __forceinline__ float2 unpk2(u64t v) {
    unsigned lo, hi; asm("mov.b64 {%0, %1}, %2;" : "=r"(lo), "=r"(hi) : "l"(v));
    return make_float2(__uint_as_float(lo), __uint_as_float(hi));
}
__device__ __forceinline__ u64t pk2(float x, float y) {
    u64t d; asm("mov.b64 %0, {%1, %2};" : "=l"(d) : "r"(__float_as_uint(x)), "r"(__float_as_uint(y)));
    return d;
}

// ---- DSMEM / mbarrier helpers -----------------------------------------------
__device__ __forceinline__ uint32_t smem_u32(const void* p) {
    return (uint32_t)__cvta_generic_to_shared(p);
}
// st.async: store into rank's SMEM + complete_tx on that rank's mbarrier.
__device__ __forceinline__ void st_async_b64(uint32_t dst, uint32_t mbar, int rank, u64t v) {
    uint32_t ra, rb;
    asm volatile("mapa.shared::cluster.u32 %0, %1, %2;" : "=r"(ra) : "r"(dst),  "r"(rank));
    asm volatile("mapa.shared::cluster.u32 %0, %1, %2;" : "=r"(rb) : "r"(mbar), "r"(rank));
    asm volatile("st.async.shared::cluster.mbarrier::complete_tx::bytes.b64 [%0], %1, [%2];"
                 :: "r"(ra), "l"(v), "r"(rb) : "memory");
}
__device__ __forceinline__ void mbar_init(uint32_t mbar, unsigned count) {
    asm volatile("mbarrier.init.shared.b64 [%0], %1;" :: "r"(mbar), "r"(count) : "memory");
}
__device__ __forceinline__ void mbar_expect_tx(uint32_t mbar, unsigned bytes) {
    asm volatile("mbarrier.arrive.expect_tx.shared.b64 _, [%0], %1;"
                 :: "r"(mbar), "r"(bytes) : "memory");
}
__device__ __forceinline__ void mbar_wait_parity(uint32_t mbar, unsigned parity) {
    unsigned done = 0;
    while (!done) {
        asm volatile("{\n\t.reg .pred p;\n\t"
                     "mbarrier.try_wait.parity.acquire.cluster.shared::cta.b64 p, [%1], %2, 0x989680;\n\t"
                     "selp.b32 %0, 1, 0, p;\n\t}"
                     : "=r"(done) : "r"(mbar), "r"(parity) : "memory");
    }
}
__device__ __forceinline__ void cluster_sync_hw() {
    asm volatile("barrier.cluster.arrive.aligned;" ::: "memory");
    asm volatile("barrier.cluster.wait.aligned;"   ::: "memory");
}

// h_new[b][j] = tanh( xp[b][t][j] + sum_k h[b][k]*Whh[j][k] )
// R9 compute verbatim; exchange via st.async (tx-counted mbarrier) instead of
// barrier.cluster: no fence, no release-drain, ~90cyc try_wait instead of
// ~490cyc UCGABAR_WAIT. Two alternating barriers give the 1-step skew the
// dataflow permits; expect_tx for step s+2 is issued right after wait(s)
// (tid0 is a scatter participant -> remote s+2 stores provably follow it).
__global__ void __launch_bounds__(RTHREADS, 1) __cluster_dims__(G_J, 1, 1)
rnn_kernel(const float* __restrict__ xp, const float* __restrict__ Whh,
           float* __restrict__ outseq, int store_out)
{
    __shared__ float2 s_h[2][2][NH];    // [buf][pair(b01/b23)][j]  (16 KB)
    __shared__ __align__(8) unsigned long long s_mbar[2];

    const int tid    = threadIdx.x;
    const int w      = tid >> 5;
    const int lane   = tid & 31;
    const int gb     = blockIdx.x >> 3;          // batch group / cluster id
    const int gj     = blockIdx.x & 7;           // rank within cluster
    const int b_base = gb * 4;
    const int j_base = gj * CTA_J;

    // ---- W slice in registers: wreg[kk][i] = Whh[j_base+w*8+i][lane+32kk] ---
    float wreg[16][8];
    #pragma unroll
    for (int i = 0; i < 8; i++) {
        const float* wrow = Whh + (j_base + w * 8 + i) * NH + lane;
        #pragma unroll
        for (int kk = 0; kk < 16; kk++)
            wreg[kk][i] = __ldg(wrow + 32 * kk);
    }

    const uint32_t mb[2] = { smem_u32(&s_mbar[0]), smem_u32(&s_mbar[1]) };

    // init barriers + zero h buffer 0
    if (tid == 0) {
        mbar_init(mb[0], 1);
        mbar_init(mb[1], 1);
        // pre-post expects for data steps s=1 (mb[1]) and s=2 (mb[0])
        mbar_expect_tx(mb[1], STEP_TX);
        mbar_expect_tx(mb[0], STEP_TX);
        asm volatile("fence.mbarrier_init.release.cluster;" ::: "memory");
    }
    for (int idx = tid; idx < NH; idx += RTHREADS) {
        s_h[0][0][idx] = make_float2(0.f, 0.f);
        s_h[0][1][idx] = make_float2(0.f, 0.f);
    }
    __syncthreads();
    cluster_sync_hw();     // peers' SMEM + barriers valid before any st.async

    // thread's output index after the warp reduce-scatter
    const int b4 = (lane >> 4) & 1, b3 = (lane >> 3) & 1, b2 = (lane >> 2) & 1;
    const int p_fin = (lane >> 1) & 1;            // batch pair (b01 vs b23)
    const int i_fin = 4 * b4 + 2 * b3 + b2;       // j offset within warp group
    const int jglb  = j_base + w * 8 + i_fin;     // global j (0..511)
    const int bb0   = b_base + p_fin * 2;
    const uint32_t dst_addr[2] = { smem_u32(&s_h[0][p_fin][jglb]),
                                   smem_u32(&s_h[1][p_fin][jglb]) };
    const int r0 = (lane & 1) ? 4 : 0;            // lane parity splits 8 ranks

    unsigned par0 = 0, par1 = 0;                  // parity trackers per barrier

    #pragma unroll 1
    for (int t = 0; t < NT; ++t) {
        const int cur = t & 1, nxt = cur ^ 1;

        // xp prefetch for this thread's outputs (exchange-independent)
        const int rowA = (bb0 * NT + t) * NH + jglb;
        const int rowB = ((bb0 + 1) * NT + t) * NH + jglb;
        const float xvA = __ldg(xp + rowA);
        const float xvB = __ldg(xp + rowB);

        // ---- packed-FMA partials over this lane's k subset ------------------
        u64t a[16];
        #pragma unroll
        for (int m = 0; m < 16; m++) a[m] = 0ull;

        #pragma unroll
        for (int kk = 0; kk < 16; kk++) {
            const int k = lane + 32 * kk;
            const u64t h01 = *(const u64t*)&s_h[cur][0][k];
            const u64t h23 = *(const u64t*)&s_h[cur][1][k];
            #pragma unroll
            for (int i = 0; i < 8; i++) {
                const u64t wp = bcast2(wreg[kk][i]);
                a[i * 2 + 0] = fmax2(wp, h01, a[i * 2 + 0]);
                a[i * 2 + 1] = fmax2(wp, h23, a[i * 2 + 1]);
            }
        }

        // ---- in-warp reduce-scatter (k-split across 32 lanes) ---------------
        u64t v8[8];
        #pragma unroll
        for (int m = 0; m < 8; m++) {
            const u64t send = (lane & 16) ? a[m] : a[m + 8];
            const u64t kept = (lane & 16) ? a[m + 8] : a[m];
            v8[m] = addx2(kept, __shfl_xor_sync(0xffffffffu, send, 16));
        }
        u64t v4[4];
        #pragma unroll
        for (int m = 0; m < 4; m++) {
            const u64t send = (lane & 8) ? v8[m] : v8[m + 4];
            const u64t kept = (lane & 8) ? v8[m + 4] : v8[m];
            v4[m] = addx2(kept, __shfl_xor_sync(0xffffffffu, send, 8));
        }
        u64t v2[2];
        #pragma unroll
        for (int m = 0; m < 2; m++) {
            const u64t send = (lane & 4) ? v4[m] : v4[m + 2];
            const u64t kept = (lane & 4) ? v4[m + 2] : v4[m];
            v2[m] = addx2(kept, __shfl_xor_sync(0xffffffffu, send, 4));
        }
        u64t v1;
        {
            const u64t send = (lane & 2) ? v2[0] : v2[1];
            const u64t kept = (lane & 2) ? v2[1] : v2[0];
            v1 = addx2(kept, __shfl_xor_sync(0xffffffffu, send, 2));
        }
        v1 = addx2(v1, __shfl_xor_sync(0xffffffffu, v1, 1));  // lanes l,l^1 dup

        // ---- activation -----------------------------------------------------
        const float2 s  = unpk2(v1);
        const float  h0 = tanhf(s.x + xvA);
        const float  h1 = tanhf(s.y + xvB);
        const u64t   hv = pk2(h0, h1);

        // side outputs (odd lanes)
        if (lane & 1) {
            if (store_out) { outseq[rowA] = h0; outseq[rowB] = h1; }
            if (t == NT - 1) { g_hfin[bb0][jglb] = h0; g_hfin[bb0 + 1][jglb] = h1; }
        }

        if (t < NT - 1) {
            // scatter h(t+1) into all 8 cluster CTAs' buf[nxt] with tx-signal
            const uint32_t da  = dst_addr[nxt];
            const uint32_t mbx = mb[nxt];           // (t+1)&1 == nxt
            #pragma unroll
            for (int r = 0; r < 4; r++)
                st_async_b64(da, mbx, r0 + r, hv);

            // wait for everyone's h(t+1) (incl. our own stores)
            if (nxt == 0) { mbar_wait_parity(mb[0], par0); par0 ^= 1; }
            else          { mbar_wait_parity(mb[1], par1); par1 ^= 1; }

            // re-arm this barrier for data step t+3 (same barrier, next phase)
            if (tid == 0 && t + 3 <= NT - 1)
                mbar_expect_tx(mbx, STEP_TX);
        }
    }
}

// ---- tf32 tensor-core GEMM: C[M,N] = A[M,K] @ B[N,K]^T + bias1 (+bias2) -----
// mma.sync.m16n8k8 tf32. CTA tile 128x64, BK=32, 256 thr = 8 warps (2m x 4n).
#define TBM 128
#define TBN 64
#define TBK 32
#define TPAD 4

__device__ __forceinline__ unsigned tf32b(float f) {
    unsigned r; asm("cvt.rna.tf32.f32 %0, %1;" : "=r"(r) : "f"(f));
    return r;
}

__global__ void __launch_bounds__(256)
gemm_tf32_nt_bias(const float* __restrict__ A, const float* __restrict__ B,
                  const float* __restrict__ bias1, const float* __restrict__ bias2,
                  float* __restrict__ C, int M, int N, int K)
{
    __shared__ unsigned As[TBK][TBM + TPAD];   // tf32 bits, [k][m]
    __shared__ unsigned Bs[TBK][TBN + TPAD];   // tf32 bits, [k][n]

    const int tid    = threadIdx.x;
    const int warp   = tid >> 5;
    const int lane   = tid & 31;
    const int warp_m = warp >> 2;          // 0..1 -> m offset *64
    const int warp_n = warp & 3;           // 0..3 -> n offset *16
    const int gid    = lane >> 2;          // 0..7
    const int tig    = lane & 3;           // 0..3

    const int m0 = blockIdx.x * TBM;
    const int n0 = blockIdx.y * TBN;

    const int lrA = tid >> 1;              // m row 0..127
    const int lcA = (tid & 1) * 16;        // k col base
    const int lrB = tid >> 2;              // n row 0..63
    const int lcB = (tid & 3) * 8;         // k col base

    float acc[4][2][4];
    #pragma unroll
    for (int mi = 0; mi < 4; mi++)
        #pragma unroll
        for (int ni = 0; ni < 2; ni++)
            #pragma unroll
            for (int c = 0; c < 4; c++) acc[mi][ni][c] = 0.f;

    for (int k0 = 0; k0 < K; k0 += TBK) {
        float4 a4[4], b4[2];
        #pragma unroll
        for (int c = 0; c < 4; c++)
            a4[c] = *(const float4*)(A + (m0 + lrA) * K + k0 + lcA + c * 4);
        #pragma unroll
        for (int c = 0; c < 2; c++)
            b4[c] = *(const float4*)(B + (n0 + lrB) * K + k0 + lcB + c * 4);

        __syncthreads();
        #pragma unroll
        for (int c = 0; c < 4; c++) {
            As[lcA + c * 4 + 0][lrA] = tf32b(a4[c].x);
            As[lcA + c * 4 + 1][lrA] = tf32b(a4[c].y);
            As[lcA + c * 4 + 2][lrA] = tf32b(a4[c].z);
            As[lcA + c * 4 + 3][lrA] = tf32b(a4[c].w);
        }
        #pragma unroll
        for (int c = 0; c < 2; c++) {
            Bs[lcB + c * 4 + 0][lrB] = tf32b(b4[c].x);
            Bs[lcB + c * 4 + 1][lrB] = tf32b(b4[c].y);
            Bs[lcB + c * 4 + 2][lrB] = tf32b(b4[c].z);
            Bs[lcB + c * 4 + 3][lrB] = tf32b(b4[c].w);
        }
        __syncthreads();

        #pragma unroll
        for (int ks = 0; ks < TBK / 8; ks++) {
            const int kb = ks * 8;
            unsigned af[4][4], bf[2][2];
            #pragma unroll
            for (int mi = 0; mi < 4; mi++) {
                const int mr = warp_m * 64 + mi * 16;
                af[mi][0] = As[kb + tig    ][mr + gid];
                af[mi][1] = As[kb + tig    ][mr + gid + 8];
                af[mi][2] = As[kb + tig + 4][mr + gid];
                af[mi][3] = As[kb + tig + 4][mr + gid + 8];
            }
            #pragma unroll
            for (int ni = 0; ni < 2; ni++) {
                const int nc = warp_n * 16 + ni * 8;
                bf[ni][0] = Bs[kb + tig    ][nc + gid];
                bf[ni][1] = Bs[kb + tig + 4][nc + gid];
            }
            #pragma unroll
            for (int mi = 0; mi < 4; mi++)
                #pragma unroll
                for (int ni = 0; ni < 2; ni++) {
                    asm volatile(
                        "mma.sync.aligned.m16n8k8.row.col.f32.tf32.tf32.f32 "
                        "{%0,%1,%2,%3}, {%4,%5,%6,%7}, {%8,%9}, {%0,%1,%2,%3};"
                        : "+f"(acc[mi][ni][0]), "+f"(acc[mi][ni][1]),
                          "+f"(acc[mi][ni][2]), "+f"(acc[mi][ni][3])
                        : "r"(af[mi][0]), "r"(af[mi][1]), "r"(af[mi][2]), "r"(af[mi][3]),
                          "r"(bf[ni][0]), "r"(bf[ni][1]));
                }
        }
    }

    #pragma unroll
    for (int ni = 0; ni < 2; ni++) {
        const int col = n0 + warp_n * 16 + ni * 8 + tig * 2;
        float bv0 = bias1 ? bias1[col]     : 0.f;
        float bv1 = bias1 ? bias1[col + 1] : 0.f;
        if (bias2) { bv0 += bias2[col]; bv1 += bias2[col + 1]; }
        #pragma unroll
        for (int mi = 0; mi < 4; mi++) {
            const int row = m0 + warp_m * 64 + mi * 16 + gid;
            *(float2*)(C + row * N + col) =
                make_float2(acc[mi][ni][0] + bv0, acc[mi][ni][1] + bv1);
            *(float2*)(C + (row + 8) * N + col) =
                make_float2(acc[mi][ni][2] + bv0, acc[mi][ni][3] + bv1);
        }
    }
}

// ---- small fp32 GEMM (64x64 tile) for the final projection (M=64) -----------
#define BM 64
#define BN 64
#define BK 16

__global__ void __launch_bounds__(256)
gemm_nt_bias(const float* __restrict__ A, const float* __restrict__ B,
             const float* __restrict__ bias1, const float* __restrict__ bias2,
             float* __restrict__ C, int M, int N, int K)
{
    __shared__ __align__(16) float As[BK][BM];
    __shared__ __align__(16) float Bs[BK][BN];

    const int tid = threadIdx.x;
    const int m0 = blockIdx.x * BM;
    const int n0 = blockIdx.y * BN;
    const int tx = tid & 15;
    const int ty = tid >> 4;
    const int lr = tid >> 2;
    const int lc = tid & 3;

    float acc[4][4];
    #pragma unroll
    for (int i = 0; i < 4; i++)
        #pragma unroll
        for (int j = 0; j < 4; j++) acc[i][j] = 0.f;

    for (int kk0 = 0; kk0 < K; kk0 += BK) {
        const float4 av = *(const float4*)(A + (m0 + lr) * K + kk0 + lc * 4);
        const float4 bv = *(const float4*)(B + (n0 + lr) * K + kk0 + lc * 4);
        __syncthreads();
        As[lc*4+0][lr] = av.x; As[lc*4+1][lr] = av.y;
        As[lc*4+2][lr] = av.z; As[lc*4+3][lr] = av.w;
        Bs[lc*4+0][lr] = bv.x; Bs[lc*4+1][lr] = bv.y;
        Bs[lc*4+2][lr] = bv.z; Bs[lc*4+3][lr] = bv.w;
        __syncthreads();

        #pragma unroll
        for (int k = 0; k < BK; ++k) {
            const float4 a = *(const float4*)(&As[k][ty * 4]);
            const float4 b = *(const float4*)(&Bs[k][tx * 4]);
            const float avv[4] = {a.x, a.y, a.z, a.w};
            const float bvv[4] = {b.x, b.y, b.z, b.w};
            #pragma unroll
            for (int i = 0; i < 4; i++)
                #pragma unroll
                for (int j = 0; j < 4; j++)
                    acc[i][j] += avv[i] * bvv[j];
        }
    }

    #pragma unroll
    for (int i = 0; i < 4; i++) {
        const int m = m0 + ty * 4 + i;
        const int n = n0 + tx * 4;
        float bsv[4];
        #pragma unroll
        for (int j = 0; j < 4; j++) {
            bsv[j] = bias1 ? bias1[n + j] : 0.f;
            if (bias2) bsv[j] += bias2[n + j];
        }
        float4 o;
        o.x = acc[i][0] + bsv[0];
        o.y = acc[i][1] + bsv[1];
        o.z = acc[i][2] + bsv[2];
        o.w = acc[i][3] + bsv[3];
        *(float4*)(C + m * N + n) = o;
    }
}

// ---- launch -----------------------------------------------------------------
extern "C" void kernel_launch(void* const* d_in, const int* in_sizes, int n_in,
                              void* d_out, int out_size)
{
    const float* x     = (const float*)d_in[0];
    const float* W_ih0 = (const float*)d_in[1];
    const float* W_hh0 = (const float*)d_in[2];
    const float* b_ih0 = (const float*)d_in[3];
    const float* b_hh0 = (const float*)d_in[4];
    const float* W_ih1 = (const float*)d_in[5];
    const float* W_hh1 = (const float*)d_in[6];
    const float* b_ih1 = (const float*)d_in[7];
    const float* b_hh1 = (const float*)d_in[8];
    const float* W_out = (const float*)d_in[9];
    const float* b_out = (const float*)d_in[10];
    float* out = (float*)d_out;

    float *xp, *out0, *hfin;
    cudaGetSymbolAddress((void**)&xp,   g_xp);
    cudaGetSymbolAddress((void**)&out0, g_out0);
    cudaGetSymbolAddress((void**)&hfin, g_hfin);

    const int M = NB * NT;  // 32768

    // xp0 = x @ W_ih0^T + b_ih0 + b_hh0   (tf32 tensor cores)
    {
        dim3 grid(M / TBM, NH / TBN);
        gemm_tf32_nt_bias<<<grid, 256>>>(x, W_ih0, b_ih0, b_hh0, xp, M, NH, NIN);
    }
    // layer 0 recurrence (stores full sequence)
    rnn_kernel<<<NCTA, RTHREADS>>>(xp, W_hh0, out0, 1);

    // xp1 = out0 @ W_ih1^T + b_ih1 + b_hh1   (tf32 tensor cores)
    {
        dim3 grid(M / TBM, NH / TBN);
        gemm_tf32_nt_bias<<<grid, 256>>>(out0, W_ih1, b_ih1, b_hh1, xp, M, NH, NH);
    }
    // layer 1 recurrence (final hidden -> g_hfin)
    rnn_kernel<<<NCTA, RTHREADS>>>(xp, W_hh1, nullptr, 0);

    // out = h_last @ W_out^T + b_out  (tiny, fp32)
    {
        dim3 grid(NB / BM, NOUT / BN);
        gemm_nt_bias<<<grid, 256>>>(hfin, W_out, b_out, nullptr, out, NB, NOUT, NH);
    }
}

// round 15
// speedup vs baseline: 1.7158x; 1.1495x over previous
#include <cuda_runtime.h>
#include <cstdint>

#define NB   64
#define NT   512
#define NIN  256
#define NH   512
#define NOUT 256

// ---- static device scratch (no runtime allocation) --------------------------
__device__ float  g_xp[NB * NT * NH];
__device__ float  g_out0[NB * NT * NH];
__device__ float  g_hfin[NB][NH];        // final hidden, scalar layout for proj

// ---- recurrence config ------------------------------------------------------
#define G_J 8                 // CTAs per cluster (j-slices)
#define NCTA 128              // 16 clusters x 8
#define CTA_J 64
#define RTHREADS 256          // 8 warps; warp = 8-j group, lane = k subset
#define STEP_TX  7168         // bytes of REMOTE h received per CTA per step (7x1KB)

// ---- f32x2 packed helpers ---------------------------------------------------
typedef unsigned long long u64t;
__device__ __forceinline__ u64t bcast2(float w) {
    u64t d; unsigned u = __float_as_uint(w);
    asm("mov.b64 %0, {%1, %1};" : "=l"(d) : "r"(u));
    return d;
}
__device__ __forceinline__ u64t fmax2(u64t a, u64t b, u64t c) {
    u64t d; asm("fma.rn.f32x2 %0, %1, %2, %3;" : "=l"(d) : "l"(a), "l"(b), "l"(c));
    return d;
}
__device__ __forceinline__ u64t addx2(u64t a, u64t b) {
    u64t d; asm("add.rn.f32x2 %0, %1, %2;" : "=l"(d) : "l"(a), "l"(b));
    return d;
}
__device__ __forceinline__ float2 unpk2(u64t v) {
    unsigned lo, hi; asm("mov.b64 {%0, %1}, %2;" : "=r"(lo), "=r"(hi) : "l"(v));
    return make_float2(__uint_as_float(lo), __uint_as_float(hi));
}
__device__ __forceinline__ u64t pk2(float x, float y) {
    u64t d; asm("mov.b64 %0, {%1, %2};" : "=l"(d) : "r"(__float_as_uint(x)), "r"(__float_as_uint(y)));
    return d;
}

// ---- DSMEM / mbarrier helpers -----------------------------------------------
__device__ __forceinline__ uint32_t smem_u32(const void* p) {
    return (uint32_t)__cvta_generic_to_shared(p);
}
__device__ __forceinline__ uint32_t mapa_u32(uint32_t addr, int rank) {
    uint32_t ra;
    asm volatile("mapa.shared::cluster.u32 %0, %1, %2;" : "=r"(ra) : "r"(addr), "r"(rank));
    return ra;
}
// st.async with PRE-MAPPED addresses (mapa hoisted out of the loop).
__device__ __forceinline__ void st_async_pre(uint32_t ra, uint32_t rb, u64t v) {
    asm volatile("st.async.shared::cluster.mbarrier::complete_tx::bytes.b64 [%0], %1, [%2];"
                 :: "r"(ra), "l"(v), "r"(rb) : "memory");
}
__device__ __forceinline__ void sts_b64(uint32_t addr, u64t v) {
    asm volatile("st.shared.b64 [%0], %1;" :: "r"(addr), "l"(v) : "memory");
}
__device__ __forceinline__ void mbar_init(uint32_t mbar, unsigned count) {
    asm volatile("mbarrier.init.shared.b64 [%0], %1;" :: "r"(mbar), "r"(count) : "memory");
}
__device__ __forceinline__ void mbar_expect_tx(uint32_t mbar, unsigned bytes) {
    asm volatile("mbarrier.arrive.expect_tx.shared.b64 _, [%0], %1;"
                 :: "r"(mbar), "r"(bytes) : "memory");
}
__device__ __forceinline__ void mbar_wait_parity(uint32_t mbar, unsigned parity) {
    unsigned done = 0;
    while (!done) {
        asm volatile("{\n\t.reg .pred p;\n\t"
                     "mbarrier.try_wait.parity.acquire.cluster.shared::cta.b64 p, [%1], %2, 0x989680;\n\t"
                     "selp.b32 %0, 1, 0, p;\n\t}"
                     : "=r"(done) : "r"(mbar), "r"(parity) : "memory");
    }
}
__device__ __forceinline__ void cluster_sync_hw() {
    asm volatile("barrier.cluster.arrive.aligned;" ::: "memory");
    asm volatile("barrier.cluster.wait.aligned;"   ::: "memory");
}

// h_new[b][j] = tanh( xp[b][t][j] + sum_k h[b][k]*Whh[j][k] )
// R14 skeleton + own-slice-first: W registers are rotated by own rank so the
// locally-produced k-block (c=0,1) is accumulated BEFORE the mbarrier wait;
// the wait then covers only the 7 remote slices (expect_tx=7168). Own slice is
// published via plain st.shared + __syncthreads. All mapa hoisted.
__global__ void __launch_bounds__(RTHREADS, 1) __cluster_dims__(G_J, 1, 1)
rnn_kernel(const float* __restrict__ xp, const float* __restrict__ Whh,
           float* __restrict__ outseq, int store_out)
{
    __shared__ float2 s_h[2][2][NH];    // [buf][pair(b01/b23)][j]  (16 KB)
    __shared__ __align__(8) unsigned long long s_mbar[2];

    const int tid    = threadIdx.x;
    const int w      = tid >> 5;
    const int lane   = tid & 31;
    const int gb     = blockIdx.x >> 3;          // batch group / cluster id
    const int gj     = blockIdx.x & 7;           // rank within cluster
    const int b_base = gb * 4;
    const int j_base = gj * CTA_J;

    // ---- W slice in registers, ROTATED by own rank:
    // wreg[c][i] = Whh[j_base+w*8+i][ lane + 32*((2*gj + c) & 15) ]
    // -> c=0,1 correspond to k in [64*gj, 64*gj+64) (the locally produced slice)
    float wreg[16][8];
    #pragma unroll
    for (int i = 0; i < 8; i++) {
        const float* wrow = Whh + (j_base + w * 8 + i) * NH;
        #pragma unroll
        for (int c = 0; c < 16; c++)
            wreg[c][i] = __ldg(wrow + lane + ((64 * gj + 32 * c) & 511));
    }

    const uint32_t mb[2] = { smem_u32(&s_mbar[0]), smem_u32(&s_mbar[1]) };

    // init barriers + zero h buffer 0
    if (tid == 0) {
        mbar_init(mb[0], 1);
        mbar_init(mb[1], 1);
        // pre-post expects for data steps s=1 (mb[1]) and s=2 (mb[0])
        mbar_expect_tx(mb[1], STEP_TX);
        mbar_expect_tx(mb[0], STEP_TX);
        asm volatile("fence.mbarrier_init.release.cluster;" ::: "memory");
    }
    for (int idx = tid; idx < NH; idx += RTHREADS) {
        s_h[0][0][idx] = make_float2(0.f, 0.f);
        s_h[0][1][idx] = make_float2(0.f, 0.f);
    }
    __syncthreads();
    cluster_sync_hw();     // peers' SMEM + barriers valid before any st.async

    // thread's output index after the warp reduce-scatter
    const int b4 = (lane >> 4) & 1, b3 = (lane >> 3) & 1, b2 = (lane >> 2) & 1;
    const int p_fin = (lane >> 1) & 1;            // batch pair (b01 vs b23)
    const int i_fin = 4 * b4 + 2 * b3 + b2;       // j offset within warp group
    const int jglb  = j_base + w * 8 + i_fin;     // global j (0..511)
    const int bb0   = b_base + p_fin * 2;
    const uint32_t dst_addr[2] = { smem_u32(&s_h[0][p_fin][jglb]),
                                   smem_u32(&s_h[1][p_fin][jglb]) };
    const int r0 = (lane & 1) ? 4 : 0;            // lane parity splits 8 ranks

    // hoisted remote addresses for this thread's 4 destination ranks x 2 bufs
    uint32_t d_dat0[4], d_dat1[4], d_mb0[4], d_mb1[4];
    #pragma unroll
    for (int r = 0; r < 4; r++) {
        d_dat0[r] = mapa_u32(dst_addr[0], r0 + r);
        d_dat1[r] = mapa_u32(dst_addr[1], r0 + r);
        d_mb0[r]  = mapa_u32(mb[0], r0 + r);
        d_mb1[r]  = mapa_u32(mb[1], r0 + r);
    }

    unsigned par0 = 0, par1 = 0;                  // parity trackers per barrier

    #pragma unroll 1
    for (int t = 0; t < NT; ++t) {
        const int cur = t & 1, nxt = cur ^ 1;

        // xp prefetch for this thread's outputs (exchange-independent)
        const int rowA = (bb0 * NT + t) * NH + jglb;
        const int rowB = ((bb0 + 1) * NT + t) * NH + jglb;
        const float xvA = __ldg(xp + rowA);
        const float xvB = __ldg(xp + rowB);

        u64t a[16];
        #pragma unroll
        for (int m = 0; m < 16; m++) a[m] = 0ull;

        // ---- phase 1: OWN slice (c=0,1), valid via st.shared+syncthreads ----
        #pragma unroll
        for (int c = 0; c < 2; c++) {
            const int k = lane + ((64 * gj + 32 * c) & 511);
            const u64t h01 = *(const u64t*)&s_h[cur][0][k];
            const u64t h23 = *(const u64t*)&s_h[cur][1][k];
            #pragma unroll
            for (int i = 0; i < 8; i++) {
                const u64t wp = bcast2(wreg[c][i]);
                a[i * 2 + 0] = fmax2(wp, h01, a[i * 2 + 0]);
                a[i * 2 + 1] = fmax2(wp, h23, a[i * 2 + 1]);
            }
        }

        // ---- wait for the 7 remote slices of h(t), then re-arm for t+2 ------
        if (t > 0) {
            if (cur == 0) { mbar_wait_parity(mb[0], par0); par0 ^= 1; }
            else          { mbar_wait_parity(mb[1], par1); par1 ^= 1; }
            if (tid == 0 && t + 2 <= NT - 1)
                mbar_expect_tx(mb[cur], STEP_TX);
        }

        // ---- phase 2: remote slices (c=2..15) -------------------------------
        #pragma unroll
        for (int c = 2; c < 16; c++) {
            const int k = lane + ((64 * gj + 32 * c) & 511);
            const u64t h01 = *(const u64t*)&s_h[cur][0][k];
            const u64t h23 = *(const u64t*)&s_h[cur][1][k];
            #pragma unroll
            for (int i = 0; i < 8; i++) {
                const u64t wp = bcast2(wreg[c][i]);
                a[i * 2 + 0] = fmax2(wp, h01, a[i * 2 + 0]);
                a[i * 2 + 1] = fmax2(wp, h23, a[i * 2 + 1]);
            }
        }

        // ---- in-warp reduce-scatter (k-split across 32 lanes) ---------------
        u64t v8[8];
        #pragma unroll
        for (int m = 0; m < 8; m++) {
            const u64t send = (lane & 16) ? a[m] : a[m + 8];
            const u64t kept = (lane & 16) ? a[m + 8] : a[m];
            v8[m] = addx2(kept, __shfl_xor_sync(0xffffffffu, send, 16));
        }
        u64t v4[4];
        #pragma unroll
        for (int m = 0; m < 4; m++) {
            const u64t send = (lane & 8) ? v8[m] : v8[m + 4];
            const u64t kept = (lane & 8) ? v8[m + 4] : v8[m];
            v4[m] = addx2(kept, __shfl_xor_sync(0xffffffffu, send, 8));
        }
        u64t v2[2];
        #pragma unroll
        for (int m = 0; m < 2; m++) {
            const u64t send = (lane & 4) ? v4[m] : v4[m + 2];
            const u64t kept = (lane & 4) ? v4[m + 2] : v4[m];
            v2[m] = addx2(kept, __shfl_xor_sync(0xffffffffu, send, 4));
        }
        u64t v1;
        {
            const u64t send = (lane & 2) ? v2[0] : v2[1];
            const u64t kept = (lane & 2) ? v2[1] : v2[0];
            v1 = addx2(kept, __shfl_xor_sync(0xffffffffu, send, 2));
        }
        v1 = addx2(v1, __shfl_xor_sync(0xffffffffu, v1, 1));  // lanes l,l^1 dup

        // ---- activation -----------------------------------------------------
        const float2 s  = unpk2(v1);
        const float  h0 = tanhf(s.x + xvA);
        const float  h1 = tanhf(s.y + xvB);
        const u64t   hv = pk2(h0, h1);

        if (t < NT - 1) {
            // scatter h(t+1): own rank via st.shared, 7 remotes via st.async
            #pragma unroll
            for (int r = 0; r < 4; r++) {
                const int rr = r0 + r;
                if (rr == gj) {
                    sts_b64(nxt ? dst_addr[1] : dst_addr[0], hv);
                } else {
                    const uint32_t ra = nxt ? d_dat1[r] : d_dat0[r];
                    const uint32_t rb = nxt ? d_mb1[r]  : d_mb0[r];
                    st_async_pre(ra, rb, hv);
                }
            }
            __syncthreads();   // own-slice STS visible to all warps for phase 1
        }

        // side outputs (odd lanes) — off the critical path
        if (lane & 1) {
            if (store_out) { outseq[rowA] = h0; outseq[rowB] = h1; }
            if (t == NT - 1) { g_hfin[bb0][jglb] = h0; g_hfin[bb0 + 1][jglb] = h1; }
        }
    }
}

// ---- tf32 tensor-core GEMM: C[M,N] = A[M,K] @ B[N,K]^T + bias1 (+bias2) -----
// mma.sync.m16n8k8 tf32. CTA tile 128x64, BK=32, 256 thr = 8 warps (2m x 4n).
#define TBM 128
#define TBN 64
#define TBK 32
#define TPAD 4

__device__ __forceinline__ unsigned tf32b(float f) {
    unsigned r; asm("cvt.rna.tf32.f32 %0, %1;" : "=r"(r) : "f"(f));
    return r;
}

__global__ void __launch_bounds__(256)
gemm_tf32_nt_bias(const float* __restrict__ A, const float* __restrict__ B,
                  const float* __restrict__ bias1, const float* __restrict__ bias2,
                  float* __restrict__ C, int M, int N, int K)
{
    __shared__ unsigned As[TBK][TBM + TPAD];   // tf32 bits, [k][m]
    __shared__ unsigned Bs[TBK][TBN + TPAD];   // tf32 bits, [k][n]

    const int tid    = threadIdx.x;
    const int warp   = tid >> 5;
    const int lane   = tid & 31;
    const int warp_m = warp >> 2;          // 0..1 -> m offset *64
    const int warp_n = warp & 3;           // 0..3 -> n offset *16
    const int gid    = lane >> 2;          // 0..7
    const int tig    = lane & 3;           // 0..3

    const int m0 = blockIdx.x * TBM;
    const int n0 = blockIdx.y * TBN;

    const int lrA = tid >> 1;              // m row 0..127
    const int lcA = (tid & 1) * 16;        // k col base
    const int lrB = tid >> 2;              // n row 0..63
    const int lcB = (tid & 3) * 8;         // k col base

    float acc[4][2][4];
    #pragma unroll
    for (int mi = 0; mi < 4; mi++)
        #pragma unroll
        for (int ni = 0; ni < 2; ni++)
            #pragma unroll
            for (int c = 0; c < 4; c++) acc[mi][ni][c] = 0.f;

    for (int k0 = 0; k0 < K; k0 += TBK) {
        float4 a4[4], b4[2];
        #pragma unroll
        for (int c = 0; c < 4; c++)
            a4[c] = *(const float4*)(A + (m0 + lrA) * K + k0 + lcA + c * 4);
        #pragma unroll
        for (int c = 0; c < 2; c++)
            b4[c] = *(const float4*)(B + (n0 + lrB) * K + k0 + lcB + c * 4);

        __syncthreads();
        #pragma unroll
        for (int c = 0; c < 4; c++) {
            As[lcA + c * 4 + 0][lrA] = tf32b(a4[c].x);
            As[lcA + c * 4 + 1][lrA] = tf32b(a4[c].y);
            As[lcA + c * 4 + 2][lrA] = tf32b(a4[c].z);
            As[lcA + c * 4 + 3][lrA] = tf32b(a4[c].w);
        }
        #pragma unroll
        for (int c = 0; c < 2; c++) {
            Bs[lcB + c * 4 + 0][lrB] = tf32b(b4[c].x);
            Bs[lcB + c * 4 + 1][lrB] = tf32b(b4[c].y);
            Bs[lcB + c * 4 + 2][lrB] = tf32b(b4[c].z);
            Bs[lcB + c * 4 + 3][lrB] = tf32b(b4[c].w);
        }
        __syncthreads();

        #pragma unroll
        for (int ks = 0; ks < TBK / 8; ks++) {
            const int kb = ks * 8;
            unsigned af[4][4], bf[2][2];
            #pragma unroll
            for (int mi = 0; mi < 4; mi++) {
                const int mr = warp_m * 64 + mi * 16;
                af[mi][0] = As[kb + tig    ][mr + gid];
                af[mi][1] = As[kb + tig    ][mr + gid + 8];
                af[mi][2] = As[kb + tig + 4][mr + gid];
                af[mi][3] = As[kb + tig + 4][mr + gid + 8];
            }
            #pragma unroll
            for (int ni = 0; ni < 2; ni++) {
                const int nc = warp_n * 16 + ni * 8;
                bf[ni][0] = Bs[kb + tig    ][nc + gid];
                bf[ni][1] = Bs[kb + tig + 4][nc + gid];
            }
            #pragma unroll
            for (int mi = 0; mi < 4; mi++)
                #pragma unroll
                for (int ni = 0; ni < 2; ni++) {
                    asm volatile(
                        "mma.sync.aligned.m16n8k8.row.col.f32.tf32.tf32.f32 "
                        "{%0,%1,%2,%3}, {%4,%5,%6,%7}, {%8,%9}, {%0,%1,%2,%3};"
                        : "+f"(acc[mi][ni][0]), "+f"(acc[mi][ni][1]),
                          "+f"(acc[mi][ni][2]), "+f"(acc[mi][ni][3])
                        : "r"(af[mi][0]), "r"(af[mi][1]), "r"(af[mi][2]), "r"(af[mi][3]),
                          "r"(bf[ni][0]), "r"(bf[ni][1]));
                }
        }
    }

    #pragma unroll
    for (int ni = 0; ni < 2; ni++) {
        const int col = n0 + warp_n * 16 + ni * 8 + tig * 2;
        float bv0 = bias1 ? bias1[col]     : 0.f;
        float bv1 = bias1 ? bias1[col + 1] : 0.f;
        if (bias2) { bv0 += bias2[col]; bv1 += bias2[col + 1]; }
        #pragma unroll
        for (int mi = 0; mi < 4; mi++) {
            const int row = m0 + warp_m * 64 + mi * 16 + gid;
            *(float2*)(C + row * N + col) =
                make_float2(acc[mi][ni][0] + bv0, acc[mi][ni][1] + bv1);
            *(float2*)(C + (row + 8) * N + col) =
                make_float2(acc[mi][ni][2] + bv0, acc[mi][ni][3] + bv1);
        }
    }
}

// ---- small fp32 GEMM (64x64 tile) for the final projection (M=64) -----------
#define BM 64
#define BN 64
#define BK 16

__global__ void __launch_bounds__(256)
gemm_nt_bias(const float* __restrict__ A, const float* __restrict__ B,
             const float* __restrict__ bias1, const float* __restrict__ bias2,
             float* __restrict__ C, int M, int N, int K)
{
    __shared__ __align__(16) float As[BK][BM];
    __shared__ __align__(16) float Bs[BK][BN];

    const int tid = threadIdx.x;
    const int m0 = blockIdx.x * BM;
    const int n0 = blockIdx.y * BN;
    const int tx = tid & 15;
    const int ty = tid >> 4;
    const int lr = tid >> 2;
    const int lc = tid & 3;

    float acc[4][4];
    #pragma unroll
    for (int i = 0; i < 4; i++)
        #pragma unroll
        for (int j = 0; j < 4; j++) acc[i][j] = 0.f;

    for (int kk0 = 0; kk0 < K; kk0 += BK) {
        const float4 av = *(const float4*)(A + (m0 + lr) * K + kk0 + lc * 4);
        const float4 bv = *(const float4*)(B + (n0 + lr) * K + kk0 + lc * 4);
        __syncthreads();
        As[lc*4+0][lr] = av.x; As[lc*4+1][lr] = av.y;
        As[lc*4+2][lr] = av.z; As[lc*4+3][lr] = av.w;
        Bs[lc*4+0][lr] = bv.x; Bs[lc*4+1][lr] = bv.y;
        Bs[lc*4+2][lr] = bv.z; Bs[lc*4+3][lr] = bv.w;
        __syncthreads();

        #pragma unroll
        for (int k = 0; k < BK; ++k) {
            const float4 a = *(const float4*)(&As[k][ty * 4]);
            const float4 b = *(const float4*)(&Bs[k][tx * 4]);
            const float avv[4] = {a.x, a.y, a.z, a.w};
            const float bvv[4] = {b.x, b.y, b.z, b.w};
            #pragma unroll
            for (int i = 0; i < 4; i++)
                #pragma unroll
                for (int j = 0; j < 4; j++)
                    acc[i][j] += avv[i] * bvv[j];
        }
    }

    #pragma unroll
    for (int i = 0; i < 4; i++) {
        const int m = m0 + ty * 4 + i;
        const int n = n0 + tx * 4;
        float bsv[4];
        #pragma unroll
        for (int j = 0; j < 4; j++) {
            bsv[j] = bias1 ? bias1[n + j] : 0.f;
            if (bias2) bsv[j] += bias2[n + j];
        }
        float4 o;
        o.x = acc[i][0] + bsv[0];
        o.y = acc[i][1] + bsv[1];
        o.z = acc[i][2] + bsv[2];
        o.w = acc[i][3] + bsv[3];
        *(float4*)(C + m * N + n) = o;
    }
}

// ---- launch -----------------------------------------------------------------
extern "C" void kernel_launch(void* const* d_in, const int* in_sizes, int n_in,
                              void* d_out, int out_size)
{
    const float* x     = (const float*)d_in[0];
    const float* W_ih0 = (const float*)d_in[1];
    const float* W_hh0 = (const float*)d_in[2];
    const float* b_ih0 = (const float*)d_in[3];
    const float* b_hh0 = (const float*)d_in[4];
    const float* W_ih1 = (const float*)d_in[5];
    const float* W_hh1 = (const float*)d_in[6];
    const float* b_ih1 = (const float*)d_in[7];
    const float* b_hh1 = (const float*)d_in[8];
    const float* W_out = (const float*)d_in[9];
    const float* b_out = (const float*)d_in[10];
    float* out = (float*)d_out;

    float *xp, *out0, *hfin;
    cudaGetSymbolAddress((void**)&xp,   g_xp);
    cudaGetSymbolAddress((void**)&out0, g_out0);
    cudaGetSymbolAddress((void**)&hfin, g_hfin);

    const int M = NB * NT;  // 32768

    // xp0 = x @ W_ih0^T + b_ih0 + b_hh0   (tf32 tensor cores)
    {
        dim3 grid(M / TBM, NH / TBN);
        gemm_tf32_nt_bias<<<grid, 256>>>(x, W_ih0, b_ih0, b_hh0, xp, M, NH, NIN);
    }
    // layer 0 recurrence (stores full sequence)
    rnn_kernel<<<NCTA, RTHREADS>>>(xp, W_hh0, out0, 1);

    // xp1 = out0 @ W_ih1^T + b_ih1 + b_hh1   (tf32 tensor cores)
    {
        dim3 grid(M / TBM, NH / TBN);
        gemm_tf32_nt_bias<<<grid, 256>>>(out0, W_ih1, b_ih1, b_hh1, xp, M, NH, NH);
    }
    // layer 1 recurrence (final hidden -> g_hfin)
    rnn_kernel<<<NCTA, RTHREADS>>>(xp, W_hh1, nullptr, 0);

    // out = h_last @ W_out^T + b_out  (tiny, fp32)
    {
        dim3 grid(NB / BM, NOUT / BN);
        gemm_nt_bias<<<grid, 256>>>(hfin, W_out, b_out, nullptr, out, NB, NOUT, NH);
    }
}